// round 11
// baseline (speedup 1.0000x reference)
#include <cuda_runtime.h>
#include <cuda_bf16.h>
#include <cstdint>
#include <math.h>

#define Bb 16
#define Cc 256
#define Tt 8192
#define Ee 32
#define SPLIT 4

// ===== scratch (device globals; no allocation allowed) =====
__device__ float g_mean[Bb * Tt];
__device__ float g_var[Bb * Tt];
__device__ float g_invdenom[Bb];
__device__ float g_part[SPLIT][Bb * Cc * Cc];
__device__ float g_q[Bb * Cc * Ee];
__device__ float g_k[Bb * Cc * Ee];
__device__ __nv_bfloat16 g_cthi[Bb * Cc * Tt];    // centered x, t-major, hi
__device__ __nv_bfloat16 g_ctlo2[Bb * Cc * Tt];   // centered x, t-major, 2*lo
__device__ __nv_bfloat16 g_ahi[Bb * Cc * Cc];     // attn hi
__device__ __nv_bfloat16 g_alo[Bb * Cc * Cc];     // attn lo
__device__ __nv_bfloat16 g_ah2[Bb * Cc * Cc];     // 0.5 * attn hi (exact)

// ===== helpers =====
__device__ __forceinline__ uint32_t smem_u32(const void* p) {
    uint32_t a;
    asm("{ .reg .u64 t; cvta.to.shared.u64 t, %1; cvt.u32.u64 %0, t; }" : "=r"(a) : "l"(p));
    return a;
}
#define CP_ASYNC16(dst, src) \
    asm volatile("cp.async.cg.shared.global [%0], [%1], 16;" :: "r"(dst), "l"(src))
#define CP_COMMIT() asm volatile("cp.async.commit_group;" ::: "memory")
#define CP_WAIT1() asm volatile("cp.async.wait_group 1;" ::: "memory")
#define CP_WAIT0() asm volatile("cp.async.wait_group 0;" ::: "memory")

#define LDMATRIX_X4(r0, r1, r2, r3, a) \
    asm volatile("ldmatrix.sync.aligned.m8n8.x4.shared.b16 {%0,%1,%2,%3}, [%4];" \
        : "=r"(r0), "=r"(r1), "=r"(r2), "=r"(r3) : "r"(a))
#define LDMATRIX_X4T(r0, r1, r2, r3, a) \
    asm volatile("ldmatrix.sync.aligned.m8n8.x4.trans.shared.b16 {%0,%1,%2,%3}, [%4];" \
        : "=r"(r0), "=r"(r1), "=r"(r2), "=r"(r3) : "r"(a))

#define MMA16816(c0, c1, c2, c3, a0, a1, a2, a3, b0, b1) \
    asm volatile("mma.sync.aligned.m16n8k16.row.col.f32.bf16.bf16.f32 " \
        "{%0,%1,%2,%3}, {%4,%5,%6,%7}, {%8,%9}, {%0,%1,%2,%3};" \
        : "+f"(c0), "+f"(c1), "+f"(c2), "+f"(c3) \
        : "r"(a0), "r"(a1), "r"(a2), "r"(a3), "r"(b0), "r"(b1))

// K-major smem row: 64 bf16 (128B) + 16B pad = 144B (odd 16B units -> conflict-free)
#define ROWK 144
// t-major (trans) smem row: 256 bf16 (512B) + 16B pad = 528B (33 units, odd)
#define ROWT 528

// cov stage: B tile (256 x 64 K-major, Hi) + A tile (128 x 64, Lo2)
#define COV_BB (256 * ROWK)
#define COV_AB (128 * ROWK)
#define COV_STAGE (COV_BB + COV_AB)
#define COV_SMEM (3 * COV_STAGE)
// out stage: Bt tile (64 x 256 t-major) + 2 A tiles (128 x 64 K-major)
#define OUT_BB (64 * ROWT)
#define OUT_AB (128 * ROWK)
#define OUT_STAGE (OUT_BB + 2 * OUT_AB)
#define OUT_SMEM (3 * OUT_STAGE)

// ---- ldmatrix fragment loaders ----
__device__ __forceinline__ void lds_A(uint32_t buf, int m0, int lane, int ks, uint32_t a[4][4]) {
#pragma unroll
    for (int mi = 0; mi < 4; mi++) {
        uint32_t ad = buf + (m0 + mi * 16 + (lane & 15)) * ROWK + ks * 32 + ((lane >> 4) << 4);
        LDMATRIX_X4(a[mi][0], a[mi][1], a[mi][2], a[mi][3], ad);
    }
}
__device__ __forceinline__ void lds_Bn(uint32_t buf, int n0, int lane, int ks, uint32_t bf[4][4]) {
#pragma unroll
    for (int np = 0; np < 4; np++) {
        uint32_t bd = buf + (n0 + np * 16 + (lane & 7) + ((lane >> 4) << 3)) * ROWK +
                      ks * 32 + (((lane >> 3) & 1) << 4);
        LDMATRIX_X4(bf[np][0], bf[np][1], bf[np][2], bf[np][3], bd);
    }
}
__device__ __forceinline__ void lds_Bt(uint32_t buf, int n0, int lane, int ks, uint32_t bf[4][4]) {
#pragma unroll
    for (int np = 0; np < 4; np++) {
        uint32_t bd = buf + (ks * 16 + (((lane >> 3) & 1) << 3) + (lane & 7)) * ROWT +
                      (n0 + np * 16 + ((lane >> 4) << 3)) * 2;
        LDMATRIX_X4T(bf[np][0], bf[np][1], bf[np][2], bf[np][3], bd);
    }
}
__device__ __forceinline__ void mma_all(uint32_t a[4][4], uint32_t bf[4][4], float acc[4][8][4]) {
#pragma unroll
    for (int mi = 0; mi < 4; mi++)
#pragma unroll
        for (int ni = 0; ni < 8; ni++) {
            int np = ni >> 1, pp = (ni & 1) << 1;
            MMA16816(acc[mi][ni][0], acc[mi][ni][1], acc[mi][ni][2], acc[mi][ni][3],
                     a[mi][0], a[mi][1], a[mi][2], a[mi][3], bf[np][pp], bf[np][pp + 1]);
        }
}

// ---------------------------------------------------------------------------
// 1) stats: smem-free two-pass streaming. thread = one t; c-loop strided.
//    Pass 2 re-reads x (L2-resident per wave) and emits hi / 2*lo.
// ---------------------------------------------------------------------------
__global__ void __launch_bounds__(256) stats_kernel(const float* __restrict__ x) {
    int b = blockIdx.y;
    int t = blockIdx.x * 256 + threadIdx.x;
    const float* xp = x + (size_t)b * Cc * Tt + t;
    float s = 0.f, sq = 0.f;
#pragma unroll 8
    for (int c = 0; c < Cc; c++) {
        float v = xp[(size_t)c * Tt];
        s += v; sq += v * v;
    }
    float m = s * (1.0f / Cc);
    g_mean[b * Tt + t] = m;
    g_var[b * Tt + t] = (sq - (float)Cc * m * m) * (1.0f / (Cc - 1));

    __nv_bfloat16* hp = g_cthi + (size_t)b * Cc * Tt + t;
    __nv_bfloat16* lp = g_ctlo2 + (size_t)b * Cc * Tt + t;
#pragma unroll 8
    for (int c = 0; c < Cc; c++) {
        float v = xp[(size_t)c * Tt] - m;
        __nv_bfloat16 h = __float2bfloat16(v);
        hp[(size_t)c * Tt] = h;
        lp[(size_t)c * Tt] = __float2bfloat16(2.0f * (v - __bfloat162float(h)));
    }
}

// ---------------------------------------------------------------------------
// 2) denom
// ---------------------------------------------------------------------------
__global__ void denom_kernel() {
    int b = blockIdx.x, tid = threadIdx.x;
    __shared__ float red[256];
    float a = 0.f;
    for (int t = tid; t < Tt; t += 256) a += g_var[b * Tt + t];
    red[tid] = a;
    __syncthreads();
    for (int o = 128; o > 0; o >>= 1) {
        if (tid < o) red[tid] += red[tid + o];
        __syncthreads();
    }
    if (tid == 0) g_invdenom[b] = 1.0f / red[0];
}

// ---------------------------------------------------------------------------
// 3) cov: S = Hi Hi^T + Lo2 Hi^T  (B=Hi shared; A seg0 aliases B tile)
// ---------------------------------------------------------------------------
__global__ void __launch_bounds__(256, 1) cov_mma_kernel() {
    extern __shared__ char dynsmem[];
    uint32_t base = smem_u32(dynsmem);
    int tid = threadIdx.x;
    int lane = tid & 31, wid = tid >> 5;
    int cm = blockIdx.x * 128;
    int sp = blockIdx.y;
    int b = blockIdx.z;
    int m0 = (wid & 1) * 64;
    int n0 = (wid >> 1) * 64;
    const int k0 = sp * (Tt / SPLIT);
    const int NCH = (Tt / SPLIT) / 64;

    float acc[4][8][4];
#pragma unroll
    for (int i = 0; i < 4; i++)
#pragma unroll
        for (int j = 0; j < 8; j++)
#pragma unroll
            for (int k = 0; k < 4; k++) acc[i][j][k] = 0.f;

    auto load_chunk = [&](int ch, int stg) {
        int kb = k0 + ch * 64;
        uint32_t bbuf = base + stg * COV_STAGE;
        const __nv_bfloat16* hb = g_cthi + ((size_t)(b * Cc)) * Tt + kb;
        for (int i = tid; i < 2048; i += 256) {
            int r = i >> 3, s = i & 7;
            CP_ASYNC16(bbuf + r * ROWK + s * 16, hb + (size_t)r * Tt + s * 8);
        }
        uint32_t abuf = bbuf + COV_BB;
        const __nv_bfloat16* lb = g_ctlo2 + ((size_t)(b * Cc + cm)) * Tt + kb;
        for (int i = tid; i < 1024; i += 256) {
            int r = i >> 3, s = i & 7;
            CP_ASYNC16(abuf + r * ROWK + s * 16, lb + (size_t)r * Tt + s * 8);
        }
        CP_COMMIT();
    };

    load_chunk(0, 0);
    load_chunk(1, 1);

    int stg = 0;
    for (int ch = 0; ch < NCH; ch++) {
        if (ch == NCH - 1) { CP_WAIT0(); } else { CP_WAIT1(); }
        __syncthreads();
        if (ch + 2 < NCH) {
            int ns = (stg + 2 >= 3) ? (stg + 2 - 3) : (stg + 2);
            load_chunk(ch + 2, ns);
        }
        uint32_t bbuf = base + stg * COV_STAGE;
        uint32_t abuf = bbuf + COV_BB;
#pragma unroll
        for (int ks = 0; ks < 4; ks++) {
            uint32_t bf[4][4], a[4][4];
            lds_Bn(bbuf, n0, lane, ks, bf);
            lds_A(bbuf, cm + m0, lane, ks, a);   // seg0: A = Hi (alias into B tile)
            mma_all(a, bf, acc);
            lds_A(abuf, m0, lane, ks, a);        // seg1: A = Lo2
            mma_all(a, bf, acc);
        }
        stg = (stg + 1 == 3) ? 0 : stg + 1;
    }

    float* dst = g_part[sp] + ((size_t)b) * Cc * Cc;
#pragma unroll
    for (int mi = 0; mi < 4; mi++)
#pragma unroll
        for (int ni = 0; ni < 8; ni++) {
            int row = cm + m0 + mi * 16 + (lane >> 2);
            int col = n0 + ni * 8 + ((lane & 3) << 1);
            *(float2*)&dst[(size_t)row * Cc + col] = make_float2(acc[mi][ni][0], acc[mi][ni][1]);
            *(float2*)&dst[(size_t)(row + 8) * Cc + col] = make_float2(acc[mi][ni][2], acc[mi][ni][3]);
        }
}

// ---------------------------------------------------------------------------
// 4) qk (fused pcc): pcc[c,d] = (S[c,d]+S[d,c]) * 0.5 * invdenom computed
//    on the fly from split partials; then q/k projections.
// ---------------------------------------------------------------------------
__global__ void __launch_bounds__(256) qk_kernel(const float* __restrict__ qw,
                                                 const float* __restrict__ qb,
                                                 const float* __restrict__ kw,
                                                 const float* __restrict__ kb) {
    __shared__ float T1s[64][33];
    __shared__ float Ps[32][68];
    __shared__ float Ws[32][68];
    int b = blockIdx.y;
    int c0 = blockIdx.x * 64;
    int tid = threadIdx.x;
    int lr = tid >> 3, lq = tid & 7;
    int tx = tid & 15, ty = tid >> 4;
    size_t bo = (size_t)b << 16;
    float invd = 0.5f * g_invdenom[b];

    float acc[4][4];
#pragma unroll
    for (int i = 0; i < 4; i++)
#pragma unroll
        for (int j = 0; j < 4; j++) acc[i][j] = 0.f;

    for (int d0 = 0; d0 < Cc; d0 += 32) {
        // phase 1: T1 = sum_s S_part[c0+r, d0+k]  (coalesced along k) + Ws fill
        for (int idx = tid; idx < 2048; idx += 256) {
            int r = idx >> 5, k = idx & 31;
            size_t i1 = bo + (size_t)(c0 + r) * Cc + d0 + k;
            float a1 = 0.f;
#pragma unroll
            for (int s = 0; s < SPLIT; s++) a1 += g_part[s][i1];
            T1s[r][k] = a1;
        }
#pragma unroll
        for (int i = 0; i < 2; i++) {
            int r = lr + i * 32;
            const float* wsrc = (r < 32) ? (qw + (size_t)r * Cc) : (kw + (size_t)(r - 32) * Cc);
            float4 w = *(const float4*)&wsrc[d0 + lq * 4];
            Ws[lq * 4 + 0][r] = w.x; Ws[lq * 4 + 1][r] = w.y;
            Ws[lq * 4 + 2][r] = w.z; Ws[lq * 4 + 3][r] = w.w;
        }
        __syncthreads();
        // phase 2: Ps[k][r] = (T1s[r][k] + sum_s S_part[d0+k, c0+r]) * invd
        for (int idx = tid; idx < 2048; idx += 256) {
            int k = idx >> 6, r = idx & 63;
            size_t i2 = bo + (size_t)(d0 + k) * Cc + c0 + r;
            float a2 = 0.f;
#pragma unroll
            for (int s = 0; s < SPLIT; s++) a2 += g_part[s][i2];
            Ps[k][r] = (T1s[r][k] + a2) * invd;
        }
        __syncthreads();
#pragma unroll
        for (int k = 0; k < 32; k++) {
            float a[4], bbv[4];
            *(float4*)(a) = *(const float4*)&Ps[k][ty * 4];
            *(float4*)(bbv) = *(const float4*)&Ws[k][tx * 4];
#pragma unroll
            for (int i = 0; i < 4; i++)
#pragma unroll
                for (int j = 0; j < 4; j++) acc[i][j] += a[i] * bbv[j];
        }
        __syncthreads();
    }
#pragma unroll
    for (int i = 0; i < 4; i++) {
        int c = c0 + ty * 4 + i;
#pragma unroll
        for (int j = 0; j < 4; j++) {
            int e = tx * 4 + j;
            if (e < 32) g_q[((size_t)b * Cc + c) * Ee + e] = acc[i][j] + qb[e];
            else g_k[((size_t)b * Cc + c) * Ee + (e - 32)] = acc[i][j] + kb[e - 32];
        }
    }
}

// ---------------------------------------------------------------------------
// 5) softmax: warp-per-row shuffle reductions; emits attn fp32 + ahi/alo/ah2
// ---------------------------------------------------------------------------
__global__ void __launch_bounds__(256) attn_kernel(float* __restrict__ attn_out) {
    __shared__ float ks[Cc][33];
    __shared__ float qs[32][33];
    int b = blockIdx.y;
    int c0 = blockIdx.x * 32;
    int tid = threadIdx.x;
    int lane = tid & 31, wid = tid >> 5;

    const float* kbp = g_k + (size_t)b * Cc * Ee;
    for (int idx = tid; idx < Cc * Ee; idx += 256) ks[idx >> 5][idx & 31] = kbp[idx];
    const float* qbp = g_q + ((size_t)b * Cc + c0) * Ee;
    for (int idx = tid; idx < 32 * Ee; idx += 256) qs[idx >> 5][idx & 31] = qbp[idx];
    __syncthreads();

    float* ab = attn_out + (size_t)b * Cc * Cc;
    __nv_bfloat16* ahp = g_ahi + (size_t)b * Cc * Cc;
    __nv_bfloat16* alp = g_alo + (size_t)b * Cc * Cc;
    __nv_bfloat16* a2p = g_ah2 + (size_t)b * Cc * Cc;

    for (int rr = 0; rr < 4; rr++) {
        int r = wid * 4 + rr;
        float sc[8];
#pragma unroll
        for (int j = 0; j < 8; j++) sc[j] = 0.f;
#pragma unroll
        for (int e = 0; e < Ee; e++) {
            float qv = qs[r][e];
#pragma unroll
            for (int j = 0; j < 8; j++) sc[j] += qv * ks[j * 32 + lane][e];
        }
        float mx = -1e30f;
#pragma unroll
        for (int j = 0; j < 8; j++) { sc[j] *= 0.0625f; mx = fmaxf(mx, sc[j]); }
#pragma unroll
        for (int o = 16; o > 0; o >>= 1) mx = fmaxf(mx, __shfl_xor_sync(0xffffffffu, mx, o));
        float sum = 0.f;
#pragma unroll
        for (int j = 0; j < 8; j++) { sc[j] = expf(sc[j] - mx); sum += sc[j]; }
#pragma unroll
        for (int o = 16; o > 0; o >>= 1) sum += __shfl_xor_sync(0xffffffffu, sum, o);
        float inv = 1.0f / sum;
        size_t rowo = (size_t)(c0 + r) * Cc;
#pragma unroll
        for (int j = 0; j < 8; j++) {
            int d = j * 32 + lane;
            float av = sc[j] * inv;
            ab[rowo + d] = av;
            __nv_bfloat16 h = __float2bfloat16(av);
            float hf = __bfloat162float(h);
            ahp[rowo + d] = h;
            alp[rowo + d] = __float2bfloat16(av - hf);
            a2p[rowo + d] = __float2bfloat16(0.5f * hf);  // exact (exponent shift)
        }
    }
}

// ---------------------------------------------------------------------------
// 6) out = ahi*Hi + alo*Hi + ah2*Lo2 + mean  (B via ldmatrix.trans from t-major)
// ---------------------------------------------------------------------------
__global__ void __launch_bounds__(256, 1) out_mma_kernel(float* __restrict__ out) {
    extern __shared__ char dynsmem[];
    uint32_t base = smem_u32(dynsmem);
    int tid = threadIdx.x;
    int lane = tid & 31, wid = tid >> 5;
    int t0 = blockIdx.x * 256;
    int cm = blockIdx.y * 128;
    int b = blockIdx.z;
    int m0 = (wid & 1) * 64;
    int n0 = (wid >> 1) * 64;
    const int NCH = 8;

    float acc[4][8][4];
#pragma unroll
    for (int i = 0; i < 4; i++)
#pragma unroll
        for (int j = 0; j < 8; j++)
#pragma unroll
            for (int k = 0; k < 4; k++) acc[i][j][k] = 0.f;

    auto load_chunk = [&](int ch, int stg) {
        int d0 = (ch >> 1) * 64;
        int type = ch & 1;
        uint32_t bbuf = base + stg * OUT_STAGE;
        const __nv_bfloat16* bt = (type ? g_ctlo2 : g_cthi) + ((size_t)(b * Cc + d0)) * Tt + t0;
        for (int i = tid; i < 2048; i += 256) {
            int r = i >> 5, s = i & 31;
            CP_ASYNC16(bbuf + r * ROWT + s * 16, bt + (size_t)r * Tt + s * 8);
        }
        uint32_t a0 = bbuf + OUT_BB;
        if (type == 0) {
            const __nv_bfloat16* ah = g_ahi + ((size_t)(b * Cc + cm)) * Cc + d0;
            for (int i = tid; i < 1024; i += 256) {
                int r = i >> 3, s = i & 7;
                CP_ASYNC16(a0 + r * ROWK + s * 16, ah + r * Cc + s * 8);
            }
            const __nv_bfloat16* al = g_alo + ((size_t)(b * Cc + cm)) * Cc + d0;
            uint32_t a1 = a0 + OUT_AB;
            for (int i = tid; i < 1024; i += 256) {
                int r = i >> 3, s = i & 7;
                CP_ASYNC16(a1 + r * ROWK + s * 16, al + r * Cc + s * 8);
            }
        } else {
            const __nv_bfloat16* a2 = g_ah2 + ((size_t)(b * Cc + cm)) * Cc + d0;
            for (int i = tid; i < 1024; i += 256) {
                int r = i >> 3, s = i & 7;
                CP_ASYNC16(a0 + r * ROWK + s * 16, a2 + r * Cc + s * 8);
            }
        }
        CP_COMMIT();
    };

    load_chunk(0, 0);
    load_chunk(1, 1);

    int stg = 0;
    for (int ch = 0; ch < NCH; ch++) {
        if (ch == NCH - 1) { CP_WAIT0(); } else { CP_WAIT1(); }
        __syncthreads();
        if (ch + 2 < NCH) {
            int ns = (stg + 2 >= 3) ? (stg + 2 - 3) : (stg + 2);
            load_chunk(ch + 2, ns);
        }
        uint32_t bbuf = base + stg * OUT_STAGE;
        uint32_t a0buf = bbuf + OUT_BB;
        int type = ch & 1;
#pragma unroll
        for (int ks = 0; ks < 4; ks++) {
            uint32_t bf[4][4], a[4][4];
            lds_Bt(bbuf, n0, lane, ks, bf);
            lds_A(a0buf, m0, lane, ks, a);
            mma_all(a, bf, acc);
            if (type == 0) {
                lds_A(a0buf + OUT_AB, m0, lane, ks, a);
                mma_all(a, bf, acc);
            }
        }
        stg = (stg + 1 == 3) ? 0 : stg + 1;
    }

#pragma unroll
    for (int mi = 0; mi < 4; mi++)
#pragma unroll
        for (int ni = 0; ni < 8; ni++) {
            int row = cm + m0 + mi * 16 + (lane >> 2);       // c
            int col = t0 + n0 + ni * 8 + ((lane & 3) << 1);  // t
            float m0v = g_mean[b * Tt + col];
            float m1v = g_mean[b * Tt + col + 1];
            *(float2*)&out[((size_t)(b * Cc + row)) * Tt + col] =
                make_float2(acc[mi][ni][0] + m0v, acc[mi][ni][1] + m1v);
            *(float2*)&out[((size_t)(b * Cc + row + 8)) * Tt + col] =
                make_float2(acc[mi][ni][2] + m0v, acc[mi][ni][3] + m1v);
        }
}

// ---------------------------------------------------------------------------
extern "C" void kernel_launch(void* const* d_in, const int* in_sizes, int n_in,
                              void* d_out, int out_size) {
    const float* x = (const float*)d_in[0];
    const float* qw = (const float*)d_in[1];
    const float* qb = (const float*)d_in[2];
    const float* kw = (const float*)d_in[3];
    const float* kb = (const float*)d_in[4];
    float* out = (float*)d_out;
    float* attn = out + (size_t)Bb * Cc * Tt;  // outputs packed: (out, attn)

    cudaFuncSetAttribute(cov_mma_kernel, cudaFuncAttributeMaxDynamicSharedMemorySize, COV_SMEM);
    cudaFuncSetAttribute(out_mma_kernel, cudaFuncAttributeMaxDynamicSharedMemorySize, OUT_SMEM);

    stats_kernel<<<dim3(Tt / 256, Bb), 256>>>(x);
    denom_kernel<<<Bb, 256>>>();
    cov_mma_kernel<<<dim3(2, SPLIT, Bb), 256, COV_SMEM>>>();
    qk_kernel<<<dim3(Cc / 64, Bb), 256>>>(qw, qb, kw, kb);
    attn_kernel<<<dim3(Cc / 32, Bb), 256>>>(attn);
    out_mma_kernel<<<dim3(Tt / 256, Cc / 128, Bb), 256, OUT_SMEM>>>(out);
}

// round 14
// speedup vs baseline: 1.0463x; 1.0463x over previous
#include <cuda_runtime.h>
#include <cuda_bf16.h>
#include <cstdint>
#include <math.h>

#define Bb 16
#define Cc 256
#define Tt 8192
#define Ee 32
#define SPLIT 4

// ===== scratch (device globals; no allocation allowed) =====
__device__ float g_mean[Bb * Tt];
__device__ float g_var[Bb * Tt];
__device__ float g_invdenom[Bb];
__device__ float g_part[SPLIT][Bb * Cc * Cc];
__device__ float g_pcc[Bb * Cc * Cc];
__device__ float g_q[Bb * Cc * Ee];
__device__ float g_k[Bb * Cc * Ee];
__device__ __nv_bfloat16 g_cthi[Bb * Cc * Tt];    // centered x, t-major, hi
__device__ __nv_bfloat16 g_ctlo2[Bb * Cc * Tt];   // centered x, t-major, 2*lo
__device__ __nv_bfloat16 g_ahi[Bb * Cc * Cc];     // attn hi
__device__ __nv_bfloat16 g_alo[Bb * Cc * Cc];     // attn lo
__device__ __nv_bfloat16 g_ah2[Bb * Cc * Cc];     // 0.5 * attn hi (exact)

// ===== helpers =====
__device__ __forceinline__ uint32_t smem_u32(const void* p) {
    uint32_t a;
    asm("{ .reg .u64 t; cvta.to.shared.u64 t, %1; cvt.u32.u64 %0, t; }" : "=r"(a) : "l"(p));
    return a;
}
#define CP_ASYNC16(dst, src) \
    asm volatile("cp.async.cg.shared.global [%0], [%1], 16;" :: "r"(dst), "l"(src))
#define CP_COMMIT() asm volatile("cp.async.commit_group;" ::: "memory")
#define CP_WAIT1() asm volatile("cp.async.wait_group 1;" ::: "memory")
#define CP_WAIT0() asm volatile("cp.async.wait_group 0;" ::: "memory")

#define LDMATRIX_X4(r0, r1, r2, r3, a) \
    asm volatile("ldmatrix.sync.aligned.m8n8.x4.shared.b16 {%0,%1,%2,%3}, [%4];" \
        : "=r"(r0), "=r"(r1), "=r"(r2), "=r"(r3) : "r"(a))
#define LDMATRIX_X4T(r0, r1, r2, r3, a) \
    asm volatile("ldmatrix.sync.aligned.m8n8.x4.trans.shared.b16 {%0,%1,%2,%3}, [%4];" \
        : "=r"(r0), "=r"(r1), "=r"(r2), "=r"(r3) : "r"(a))

#define MMA16816(c0, c1, c2, c3, a0, a1, a2, a3, b0, b1) \
    asm volatile("mma.sync.aligned.m16n8k16.row.col.f32.bf16.bf16.f32 " \
        "{%0,%1,%2,%3}, {%4,%5,%6,%7}, {%8,%9}, {%0,%1,%2,%3};" \
        : "+f"(c0), "+f"(c1), "+f"(c2), "+f"(c3) \
        : "r"(a0), "r"(a1), "r"(a2), "r"(a3), "r"(b0), "r"(b1))

// K-major smem row: 64 bf16 (128B) + 16B pad = 144B (odd 16B units -> conflict-free)
#define ROWK 144
// t-major (trans) smem row: 256 bf16 (512B) + 16B pad = 528B (33 units, odd)
#define ROWT 528

// cov stage: B tile (256 x 64 K-major, Hi) + A tile (128 x 64, Lo2)
#define COV_BB (256 * ROWK)
#define COV_AB (128 * ROWK)
#define COV_STAGE (COV_BB + COV_AB)
#define COV_SMEM (3 * COV_STAGE)
// out stage: Bt tile (64 x 256 t-major) + 2 A tiles (128 x 64 K-major)
#define OUT_BB (64 * ROWT)
#define OUT_AB (128 * ROWK)
#define OUT_STAGE (OUT_BB + 2 * OUT_AB)
#define OUT_SMEM (3 * OUT_STAGE)

// ---- ldmatrix fragment loaders ----
__device__ __forceinline__ void lds_A(uint32_t buf, int m0, int lane, int ks, uint32_t a[4][4]) {
#pragma unroll
    for (int mi = 0; mi < 4; mi++) {
        uint32_t ad = buf + (m0 + mi * 16 + (lane & 15)) * ROWK + ks * 32 + ((lane >> 4) << 4);
        LDMATRIX_X4(a[mi][0], a[mi][1], a[mi][2], a[mi][3], ad);
    }
}
__device__ __forceinline__ void lds_Bn(uint32_t buf, int n0, int lane, int ks, uint32_t bf[4][4]) {
#pragma unroll
    for (int np = 0; np < 4; np++) {
        uint32_t bd = buf + (n0 + np * 16 + (lane & 7) + ((lane >> 4) << 3)) * ROWK +
                      ks * 32 + (((lane >> 3) & 1) << 4);
        LDMATRIX_X4(bf[np][0], bf[np][1], bf[np][2], bf[np][3], bd);
    }
}
__device__ __forceinline__ void lds_Bt(uint32_t buf, int n0, int lane, int ks, uint32_t bf[4][4]) {
#pragma unroll
    for (int np = 0; np < 4; np++) {
        uint32_t bd = buf + (ks * 16 + (((lane >> 3) & 1) << 3) + (lane & 7)) * ROWT +
                      (n0 + np * 16 + ((lane >> 4) << 3)) * 2;
        LDMATRIX_X4T(bf[np][0], bf[np][1], bf[np][2], bf[np][3], bd);
    }
}
__device__ __forceinline__ void mma_all(uint32_t a[4][4], uint32_t bf[4][4], float acc[4][8][4]) {
#pragma unroll
    for (int mi = 0; mi < 4; mi++)
#pragma unroll
        for (int ni = 0; ni < 8; ni++) {
            int np = ni >> 1, pp = (ni & 1) << 1;
            MMA16816(acc[mi][ni][0], acc[mi][ni][1], acc[mi][ni][2], acc[mi][ni][3],
                     a[mi][0], a[mi][1], a[mi][2], a[mi][3], bf[np][pp], bf[np][pp + 1]);
        }
}

// ---------------------------------------------------------------------------
// 1) stats: smem-free two-pass streaming. thread = one t; c-loop strided.
// ---------------------------------------------------------------------------
__global__ void __launch_bounds__(256) stats_kernel(const float* __restrict__ x) {
    int b = blockIdx.y;
    int t = blockIdx.x * 256 + threadIdx.x;
    const float* xp = x + (size_t)b * Cc * Tt + t;
    float s = 0.f, sq = 0.f;
#pragma unroll 8
    for (int c = 0; c < Cc; c++) {
        float v = xp[(size_t)c * Tt];
        s += v; sq += v * v;
    }
    float m = s * (1.0f / Cc);
    g_mean[b * Tt + t] = m;
    g_var[b * Tt + t] = (sq - (float)Cc * m * m) * (1.0f / (Cc - 1));

    __nv_bfloat16* hp = g_cthi + (size_t)b * Cc * Tt + t;
    __nv_bfloat16* lp = g_ctlo2 + (size_t)b * Cc * Tt + t;
#pragma unroll 8
    for (int c = 0; c < Cc; c++) {
        float v = xp[(size_t)c * Tt] - m;
        __nv_bfloat16 h = __float2bfloat16(v);
        hp[(size_t)c * Tt] = h;
        lp[(size_t)c * Tt] = __float2bfloat16(2.0f * (v - __bfloat162float(h)));
    }
}

// ---------------------------------------------------------------------------
// 2) denom
// ---------------------------------------------------------------------------
__global__ void denom_kernel() {
    int b = blockIdx.x, tid = threadIdx.x;
    __shared__ float red[256];
    float a = 0.f;
    for (int t = tid; t < Tt; t += 256) a += g_var[b * Tt + t];
    red[tid] = a;
    __syncthreads();
    for (int o = 128; o > 0; o >>= 1) {
        if (tid < o) red[tid] += red[tid + o];
        __syncthreads();
    }
    if (tid == 0) g_invdenom[b] = 1.0f / red[0];
}

// ---------------------------------------------------------------------------
// 3) cov: S = Hi Hi^T + Lo2 Hi^T  (B=Hi shared; A seg0 aliases B tile)
// ---------------------------------------------------------------------------
__global__ void __launch_bounds__(256, 1) cov_mma_kernel() {
    extern __shared__ char dynsmem[];
    uint32_t base = smem_u32(dynsmem);
    int tid = threadIdx.x;
    int lane = tid & 31, wid = tid >> 5;
    int cm = blockIdx.x * 128;
    int sp = blockIdx.y;
    int b = blockIdx.z;
    int m0 = (wid & 1) * 64;
    int n0 = (wid >> 1) * 64;
    const int k0 = sp * (Tt / SPLIT);
    const int NCH = (Tt / SPLIT) / 64;

    float acc[4][8][4];
#pragma unroll
    for (int i = 0; i < 4; i++)
#pragma unroll
        for (int j = 0; j < 8; j++)
#pragma unroll
            for (int k = 0; k < 4; k++) acc[i][j][k] = 0.f;

    auto load_chunk = [&](int ch, int stg) {
        int kb = k0 + ch * 64;
        uint32_t bbuf = base + stg * COV_STAGE;
        const __nv_bfloat16* hb = g_cthi + ((size_t)(b * Cc)) * Tt + kb;
        for (int i = tid; i < 2048; i += 256) {
            int r = i >> 3, s = i & 7;
            CP_ASYNC16(bbuf + r * ROWK + s * 16, hb + (size_t)r * Tt + s * 8);
        }
        uint32_t abuf = bbuf + COV_BB;
        const __nv_bfloat16* lb = g_ctlo2 + ((size_t)(b * Cc + cm)) * Tt + kb;
        for (int i = tid; i < 1024; i += 256) {
            int r = i >> 3, s = i & 7;
            CP_ASYNC16(abuf + r * ROWK + s * 16, lb + (size_t)r * Tt + s * 8);
        }
        CP_COMMIT();
    };

    load_chunk(0, 0);
    load_chunk(1, 1);

    int stg = 0;
    for (int ch = 0; ch < NCH; ch++) {
        if (ch == NCH - 1) { CP_WAIT0(); } else { CP_WAIT1(); }
        __syncthreads();
        if (ch + 2 < NCH) {
            int ns = (stg + 2 >= 3) ? (stg + 2 - 3) : (stg + 2);
            load_chunk(ch + 2, ns);
        }
        uint32_t bbuf = base + stg * COV_STAGE;
        uint32_t abuf = bbuf + COV_BB;
#pragma unroll
        for (int ks = 0; ks < 4; ks++) {
            uint32_t bf[4][4], a[4][4];
            lds_Bn(bbuf, n0, lane, ks, bf);
            lds_A(bbuf, cm + m0, lane, ks, a);   // seg0: A = Hi (alias into B tile)
            mma_all(a, bf, acc);
            lds_A(abuf, m0, lane, ks, a);        // seg1: A = Lo2
            mma_all(a, bf, acc);
        }
        stg = (stg + 1 == 3) ? 0 : stg + 1;
    }

    float* dst = g_part[sp] + ((size_t)b) * Cc * Cc;
#pragma unroll
    for (int mi = 0; mi < 4; mi++)
#pragma unroll
        for (int ni = 0; ni < 8; ni++) {
            int row = cm + m0 + mi * 16 + (lane >> 2);
            int col = n0 + ni * 8 + ((lane & 3) << 1);
            *(float2*)&dst[(size_t)row * Cc + col] = make_float2(acc[mi][ni][0], acc[mi][ni][1]);
            *(float2*)&dst[(size_t)(row + 8) * Cc + col] = make_float2(acc[mi][ni][2], acc[mi][ni][3]);
        }
}

// ---------------------------------------------------------------------------
// 4) pcc = (S + S^T) * 0.5 * invdenom via tiled transpose (coalesced)
//    grid (64, Bb): 8x8 tiles of 32x32; block 256 = 32 cols x 8 rows
// ---------------------------------------------------------------------------
__global__ void __launch_bounds__(256) pcc_kernel() {
    __shared__ float s1[32][33], s2[32][33];
    int b = blockIdx.y;
    int ti = blockIdx.x >> 3, tj = blockIdx.x & 7;
    int tid = threadIdx.x;
    int col = tid & 31, r0 = tid >> 5;
    size_t bo = (size_t)b << 16;

#pragma unroll
    for (int rr = 0; rr < 4; rr++) {
        int r = r0 + rr * 8;
        size_t i1 = bo + (size_t)(ti * 32 + r) * Cc + tj * 32 + col;
        size_t i2 = bo + (size_t)(tj * 32 + r) * Cc + ti * 32 + col;
        float a1 = 0.f, a2 = 0.f;
#pragma unroll
        for (int s = 0; s < SPLIT; s++) { a1 += g_part[s][i1]; a2 += g_part[s][i2]; }
        s1[r][col] = a1;
        s2[r][col] = a2;
    }
    __syncthreads();
    float invd = 0.5f * g_invdenom[b];
#pragma unroll
    for (int rr = 0; rr < 4; rr++) {
        int r = r0 + rr * 8;
        g_pcc[bo + (size_t)(ti * 32 + r) * Cc + tj * 32 + col] =
            (s1[r][col] + s2[col][r]) * invd;
    }
}

// ---------------------------------------------------------------------------
// 5) q/k projections (small fp32 SIMT GEMM, reads g_pcc)
// ---------------------------------------------------------------------------
__global__ void __launch_bounds__(256) qk_kernel(const float* __restrict__ qw,
                                                 const float* __restrict__ qb,
                                                 const float* __restrict__ kw,
                                                 const float* __restrict__ kb) {
    __shared__ float Ps[32][68];
    __shared__ float Ws[32][68];
    int b = blockIdx.y;
    int c0 = blockIdx.x * 64;
    int tid = threadIdx.x;
    int lr = tid >> 3, lq = tid & 7;
    int tx = tid & 15, ty = tid >> 4;
    const float* pb = g_pcc + (size_t)b * Cc * Cc;

    float acc[4][4];
#pragma unroll
    for (int i = 0; i < 4; i++)
#pragma unroll
        for (int j = 0; j < 4; j++) acc[i][j] = 0.f;

    for (int d0 = 0; d0 < Cc; d0 += 32) {
#pragma unroll
        for (int i = 0; i < 2; i++) {
            int r = lr + i * 32;
            float4 v = *(const float4*)&pb[(size_t)(c0 + r) * Cc + d0 + lq * 4];
            Ps[lq * 4 + 0][r] = v.x; Ps[lq * 4 + 1][r] = v.y;
            Ps[lq * 4 + 2][r] = v.z; Ps[lq * 4 + 3][r] = v.w;
            const float* wsrc = (r < 32) ? (qw + (size_t)r * Cc) : (kw + (size_t)(r - 32) * Cc);
            float4 w = *(const float4*)&wsrc[d0 + lq * 4];
            Ws[lq * 4 + 0][r] = w.x; Ws[lq * 4 + 1][r] = w.y;
            Ws[lq * 4 + 2][r] = w.z; Ws[lq * 4 + 3][r] = w.w;
        }
        __syncthreads();
#pragma unroll
        for (int k = 0; k < 32; k++) {
            float a[4], bbv[4];
            *(float4*)(a) = *(const float4*)&Ps[k][ty * 4];
            *(float4*)(bbv) = *(const float4*)&Ws[k][tx * 4];
#pragma unroll
            for (int i = 0; i < 4; i++)
#pragma unroll
                for (int j = 0; j < 4; j++) acc[i][j] += a[i] * bbv[j];
        }
        __syncthreads();
    }
#pragma unroll
    for (int i = 0; i < 4; i++) {
        int c = c0 + ty * 4 + i;
#pragma unroll
        for (int j = 0; j < 4; j++) {
            int e = tx * 4 + j;
            if (e < 32) g_q[((size_t)b * Cc + c) * Ee + e] = acc[i][j] + qb[e];
            else g_k[((size_t)b * Cc + c) * Ee + (e - 32)] = acc[i][j] + kb[e - 32];
        }
    }
}

// ---------------------------------------------------------------------------
// 6) softmax: warp-per-row shuffle reductions; emits attn fp32 + ahi/alo/ah2
// ---------------------------------------------------------------------------
__global__ void __launch_bounds__(256) attn_kernel(float* __restrict__ attn_out) {
    __shared__ float ks[Cc][33];
    __shared__ float qs[32][33];
    int b = blockIdx.y;
    int c0 = blockIdx.x * 32;
    int tid = threadIdx.x;
    int lane = tid & 31, wid = tid >> 5;

    const float* kbp = g_k + (size_t)b * Cc * Ee;
    for (int idx = tid; idx < Cc * Ee; idx += 256) ks[idx >> 5][idx & 31] = kbp[idx];
    const float* qbp = g_q + ((size_t)b * Cc + c0) * Ee;
    for (int idx = tid; idx < 32 * Ee; idx += 256) qs[idx >> 5][idx & 31] = qbp[idx];
    __syncthreads();

    float* ab = attn_out + (size_t)b * Cc * Cc;
    __nv_bfloat16* ahp = g_ahi + (size_t)b * Cc * Cc;
    __nv_bfloat16* alp = g_alo + (size_t)b * Cc * Cc;
    __nv_bfloat16* a2p = g_ah2 + (size_t)b * Cc * Cc;

    for (int rr = 0; rr < 4; rr++) {
        int r = wid * 4 + rr;
        float sc[8];
#pragma unroll
        for (int j = 0; j < 8; j++) sc[j] = 0.f;
#pragma unroll
        for (int e = 0; e < Ee; e++) {
            float qv = qs[r][e];
#pragma unroll
            for (int j = 0; j < 8; j++) sc[j] += qv * ks[j * 32 + lane][e];
        }
        float mx = -1e30f;
#pragma unroll
        for (int j = 0; j < 8; j++) { sc[j] *= 0.0625f; mx = fmaxf(mx, sc[j]); }
#pragma unroll
        for (int o = 16; o > 0; o >>= 1) mx = fmaxf(mx, __shfl_xor_sync(0xffffffffu, mx, o));
        float sum = 0.f;
#pragma unroll
        for (int j = 0; j < 8; j++) { sc[j] = expf(sc[j] - mx); sum += sc[j]; }
#pragma unroll
        for (int o = 16; o > 0; o >>= 1) sum += __shfl_xor_sync(0xffffffffu, sum, o);
        float inv = 1.0f / sum;
        size_t rowo = (size_t)(c0 + r) * Cc;
#pragma unroll
        for (int j = 0; j < 8; j++) {
            int d = j * 32 + lane;
            float av = sc[j] * inv;
            ab[rowo + d] = av;
            __nv_bfloat16 h = __float2bfloat16(av);
            float hf = __bfloat162float(h);
            ahp[rowo + d] = h;
            alp[rowo + d] = __float2bfloat16(av - hf);
            a2p[rowo + d] = __float2bfloat16(0.5f * hf);  // exact (exponent shift)
        }
    }
}

// ---------------------------------------------------------------------------
// 7) out = ahi*Hi + alo*Hi + ah2*Lo2 + mean  (B via ldmatrix.trans from t-major)
// ---------------------------------------------------------------------------
__global__ void __launch_bounds__(256, 1) out_mma_kernel(float* __restrict__ out) {
    extern __shared__ char dynsmem[];
    uint32_t base = smem_u32(dynsmem);
    int tid = threadIdx.x;
    int lane = tid & 31, wid = tid >> 5;
    int t0 = blockIdx.x * 256;
    int cm = blockIdx.y * 128;
    int b = blockIdx.z;
    int m0 = (wid & 1) * 64;
    int n0 = (wid >> 1) * 64;
    const int NCH = 8;

    float acc[4][8][4];
#pragma unroll
    for (int i = 0; i < 4; i++)
#pragma unroll
        for (int j = 0; j < 8; j++)
#pragma unroll
            for (int k = 0; k < 4; k++) acc[i][j][k] = 0.f;

    auto load_chunk = [&](int ch, int stg) {
        int d0 = (ch >> 1) * 64;
        int type = ch & 1;
        uint32_t bbuf = base + stg * OUT_STAGE;
        const __nv_bfloat16* bt = (type ? g_ctlo2 : g_cthi) + ((size_t)(b * Cc + d0)) * Tt + t0;
        for (int i = tid; i < 2048; i += 256) {
            int r = i >> 5, s = i & 31;
            CP_ASYNC16(bbuf + r * ROWT + s * 16, bt + (size_t)r * Tt + s * 8);
        }
        uint32_t a0 = bbuf + OUT_BB;
        if (type == 0) {
            const __nv_bfloat16* ah = g_ahi + ((size_t)(b * Cc + cm)) * Cc + d0;
            for (int i = tid; i < 1024; i += 256) {
                int r = i >> 3, s = i & 7;
                CP_ASYNC16(a0 + r * ROWK + s * 16, ah + r * Cc + s * 8);
            }
            const __nv_bfloat16* al = g_alo + ((size_t)(b * Cc + cm)) * Cc + d0;
            uint32_t a1 = a0 + OUT_AB;
            for (int i = tid; i < 1024; i += 256) {
                int r = i >> 3, s = i & 7;
                CP_ASYNC16(a1 + r * ROWK + s * 16, al + r * Cc + s * 8);
            }
        } else {
            const __nv_bfloat16* a2 = g_ah2 + ((size_t)(b * Cc + cm)) * Cc + d0;
            for (int i = tid; i < 1024; i += 256) {
                int r = i >> 3, s = i & 7;
                CP_ASYNC16(a0 + r * ROWK + s * 16, a2 + r * Cc + s * 8);
            }
        }
        CP_COMMIT();
    };

    load_chunk(0, 0);
    load_chunk(1, 1);

    int stg = 0;
    for (int ch = 0; ch < NCH; ch++) {
        if (ch == NCH - 1) { CP_WAIT0(); } else { CP_WAIT1(); }
        __syncthreads();
        if (ch + 2 < NCH) {
            int ns = (stg + 2 >= 3) ? (stg + 2 - 3) : (stg + 2);
            load_chunk(ch + 2, ns);
        }
        uint32_t bbuf = base + stg * OUT_STAGE;
        uint32_t a0buf = bbuf + OUT_BB;
        int type = ch & 1;
#pragma unroll
        for (int ks = 0; ks < 4; ks++) {
            uint32_t bf[4][4], a[4][4];
            lds_Bt(bbuf, n0, lane, ks, bf);
            lds_A(a0buf, m0, lane, ks, a);
            mma_all(a, bf, acc);
            if (type == 0) {
                lds_A(a0buf + OUT_AB, m0, lane, ks, a);
                mma_all(a, bf, acc);
            }
        }
        stg = (stg + 1 == 3) ? 0 : stg + 1;
    }

#pragma unroll
    for (int mi = 0; mi < 4; mi++)
#pragma unroll
        for (int ni = 0; ni < 8; ni++) {
            int row = cm + m0 + mi * 16 + (lane >> 2);       // c
            int col = t0 + n0 + ni * 8 + ((lane & 3) << 1);  // t
            float m0v = g_mean[b * Tt + col];
            float m1v = g_mean[b * Tt + col + 1];
            *(float2*)&out[((size_t)(b * Cc + row)) * Tt + col] =
                make_float2(acc[mi][ni][0] + m0v, acc[mi][ni][1] + m1v);
            *(float2*)&out[((size_t)(b * Cc + row + 8)) * Tt + col] =
                make_float2(acc[mi][ni][2] + m0v, acc[mi][ni][3] + m1v);
        }
}

// ---------------------------------------------------------------------------
extern "C" void kernel_launch(void* const* d_in, const int* in_sizes, int n_in,
                              void* d_out, int out_size) {
    const float* x = (const float*)d_in[0];
    const float* qw = (const float*)d_in[1];
    const float* qb = (const float*)d_in[2];
    const float* kw = (const float*)d_in[3];
    const float* kb = (const float*)d_in[4];
    float* out = (float*)d_out;
    float* attn = out + (size_t)Bb * Cc * Tt;  // outputs packed: (out, attn)

    cudaFuncSetAttribute(cov_mma_kernel, cudaFuncAttributeMaxDynamicSharedMemorySize, COV_SMEM);
    cudaFuncSetAttribute(out_mma_kernel, cudaFuncAttributeMaxDynamicSharedMemorySize, OUT_SMEM);

    stats_kernel<<<dim3(Tt / 256, Bb), 256>>>(x);
    denom_kernel<<<Bb, 256>>>();
    cov_mma_kernel<<<dim3(2, SPLIT, Bb), 256, COV_SMEM>>>();
    pcc_kernel<<<dim3(64, Bb), 256>>>();
    qk_kernel<<<dim3(Cc / 64, Bb), 256>>>(qw, qb, kw, kb);
    attn_kernel<<<dim3(Cc / 32, Bb), 256>>>(attn);
    out_mma_kernel<<<dim3(Tt / 256, Cc / 128, Bb), 256, OUT_SMEM>>>(out);
}